// round 13
// baseline (speedup 1.0000x reference)
#include <cuda_runtime.h>
#include <cuda_bf16.h>
#include <cstdint>
#include <math.h>

#define EMB   768
#define NH    12
#define HD    64
#define BATCH 8
#define SEQ   1024
#define MROWS (BATCH * SEQ)      // 8192
#define QKVN  (3 * EMB)          // 2304

// 0.125 (1/sqrt(64)) * log2(e): folded into Q so softmax uses ex2
#define QSCALE 0.18033688011112042f

#define TSTRIDE ((size_t)BATCH * NH * SEQ * HD)   // elems per q/k/v tensor

// ---------------------------------------------------------------------------
// Scratch (no allocations allowed)
// ---------------------------------------------------------------------------
__device__ __align__(256) __nv_bfloat16 g_Ah[(size_t)MROWS * EMB];
__device__ __align__(256) __nv_bfloat16 g_Al[(size_t)MROWS * EMB];
__device__ __align__(256) __nv_bfloat16 g_WaTh[(size_t)QKVN * EMB];
__device__ __align__(256) __nv_bfloat16 g_WaTl[(size_t)QKVN * EMB];
__device__ __align__(256) __nv_bfloat16 g_WpTh[(size_t)EMB * EMB];
__device__ __align__(256) __nv_bfloat16 g_WpTl[(size_t)EMB * EMB];
__device__ __align__(256) __nv_bfloat16 g_Sh[3 * TSTRIDE];
__device__ __align__(256) __nv_bfloat16 g_Sl[3 * TSTRIDE];

// ---------------------------------------------------------------------------
// PTX helpers (sm_80-class only; toolchain targets plain sm_103)
// ---------------------------------------------------------------------------
__device__ __forceinline__ uint32_t smem_u32(const void* p) {
    uint32_t a;
    asm("{ .reg .u64 t; cvta.to.shared.u64 t, %1; cvt.u32.u64 %0, t; }"
        : "=r"(a) : "l"(p));
    return a;
}
__device__ __forceinline__ void cp16(uint32_t dst, const void* src) {
    asm volatile("cp.async.cg.shared.global [%0], [%1], 16;"
                 :: "r"(dst), "l"(src) : "memory");
}
#define CP_COMMIT() asm volatile("cp.async.commit_group;" ::: "memory")
#define CP_WAIT(n)  asm volatile("cp.async.wait_group %0;" :: "n"(n) : "memory")

#define LDSM_X4(r0, r1, r2, r3, addr) \
    asm volatile("ldmatrix.sync.aligned.m8n8.x4.shared.b16 {%0,%1,%2,%3}, [%4];" \
                 : "=r"(r0), "=r"(r1), "=r"(r2), "=r"(r3) : "r"(addr))
#define LDSM_X4T(r0, r1, r2, r3, addr) \
    asm volatile("ldmatrix.sync.aligned.m8n8.x4.trans.shared.b16 {%0,%1,%2,%3}, [%4];" \
                 : "=r"(r0), "=r"(r1), "=r"(r2), "=r"(r3) : "r"(addr))

__device__ __forceinline__ void mma16816(float* d,
                                         uint32_t a0, uint32_t a1, uint32_t a2, uint32_t a3,
                                         uint32_t b0, uint32_t b1) {
    asm volatile("mma.sync.aligned.m16n8k16.row.col.f32.bf16.bf16.f32 "
                 "{%0,%1,%2,%3}, {%4,%5,%6,%7}, {%8,%9}, {%0,%1,%2,%3};"
                 : "+f"(d[0]), "+f"(d[1]), "+f"(d[2]), "+f"(d[3])
                 : "r"(a0), "r"(a1), "r"(a2), "r"(a3), "r"(b0), "r"(b1));
}

__device__ __forceinline__ float ex2f(float x) {
    float y;
    asm("ex2.approx.ftz.f32 %0, %1;" : "=f"(y) : "f"(x));
    return y;
}

// Fast exact split: hi = bf16x2(p1,p0) via one cvt; residual reconstructed
// with bit ops. Numerically identical to per-element rn-convert + subtract.
__device__ __forceinline__ void split_pack(float p0, float p1, uint32_t& hi, uint32_t& lo) {
    uint32_t h;
    asm("cvt.rn.bf16x2.f32 %0, %1, %2;" : "=r"(h) : "f"(p1), "f"(p0));
    float f0 = __uint_as_float(h << 16);
    float f1 = __uint_as_float(h & 0xFFFF0000u);
    float r0 = p0 - f0;
    float r1 = p1 - f1;
    uint32_t l;
    asm("cvt.rn.bf16x2.f32 %0, %1, %2;" : "=r"(l) : "f"(r1), "f"(r0));
    hi = h; lo = l;
}

// ---------------------------------------------------------------------------
// Prologue kernels
// ---------------------------------------------------------------------------
__global__ __launch_bounds__(256) void split2(const float* __restrict__ src,
                                              __nv_bfloat16* __restrict__ hi,
                                              __nv_bfloat16* __restrict__ lo, int n)
{
    int i = blockIdx.x * blockDim.x + threadIdx.x;
    if (i < n) {
        float v = src[i];
        __nv_bfloat16 h = __float2bfloat16(v);
        hi[i] = h;
        lo[i] = __float2bfloat16(v - __bfloat162float(h));
    }
}

__global__ __launch_bounds__(256) void transpose_split(
    const float* __restrict__ W, __nv_bfloat16* __restrict__ Th,
    __nv_bfloat16* __restrict__ Tl, int K, int N)
{
    __shared__ float t[32][33];
    int k0 = blockIdx.y * 32, n0 = blockIdx.x * 32;
#pragma unroll
    for (int r = 0; r < 32; r += 8) {
        int k = k0 + threadIdx.y + r;
        int n = n0 + threadIdx.x;
        t[threadIdx.y + r][threadIdx.x] = W[(size_t)k * N + n];
    }
    __syncthreads();
#pragma unroll
    for (int r = 0; r < 32; r += 8) {
        int n = n0 + threadIdx.y + r;
        int k = k0 + threadIdx.x;
        float v = t[threadIdx.x][threadIdx.y + r];
        __nv_bfloat16 h = __float2bfloat16(v);
        Th[(size_t)n * K + k] = h;
        Tl[(size_t)n * K + k] = __float2bfloat16(v - __bfloat162float(h));
    }
}

// ---------------------------------------------------------------------------
// Fused split-3 mma.sync GEMM: C ~= AhBh + AlBh + AhBl (+bias), fp32 accum.
// CTA tile 128x96, 256 threads, 8 warps (4M x 2N), warp tile 32x48.
// Same smem layout / stages as R10 (112 KB/CTA -> 2 CTAs/SM), but 4 warps
// per SMSP to keep HMMA fed through ldsm/barrier bubbles.
// ---------------------------------------------------------------------------
#define AH_OFF      0
#define AL_OFF      16384
#define BH_OFF      32768
#define BL_OFF      45056
#define STAGE_BYTES 57344
#define GEMM_SMEM   (2 * STAGE_BYTES + 256)
#define NCHUNK      12

template <int MODE>
__global__ __launch_bounds__(256, 2) void gemm_mma(
    const __nv_bfloat16* __restrict__ Ah, const __nv_bfloat16* __restrict__ Al,
    const __nv_bfloat16* __restrict__ Bh, const __nv_bfloat16* __restrict__ Bl,
    const float* __restrict__ bias, float* __restrict__ C, int N,
    __nv_bfloat16* __restrict__ outh, __nv_bfloat16* __restrict__ outl)
{
    extern __shared__ char sm_raw[];
    const uint32_t base = (smem_u32(sm_raw) + 127) & ~127u;

    const int tid  = threadIdx.x;
    const int lane = tid & 31;
    const int w    = tid >> 5;            // 0..7
    const int wm   = w & 3;               // 0..3 -> 32-row slice
    const int wn   = w >> 2;              // 0..1 -> 48-col slice
    const int bn   = blockIdx.x;
    const int bm   = blockIdx.y;

    const __nv_bfloat16* Abh = Ah + (size_t)bm * 128 * EMB;
    const __nv_bfloat16* Abl = Al + (size_t)bm * 128 * EMB;
    const __nv_bfloat16* Bbh = Bh + (size_t)bn * 96 * EMB;
    const __nv_bfloat16* Bbl = Bl + (size_t)bn * 96 * EMB;

    float acc[2][6][4];
#pragma unroll
    for (int mt = 0; mt < 2; mt++)
#pragma unroll
        for (int nt = 0; nt < 6; nt++)
#pragma unroll
            for (int e = 0; e < 4; e++) acc[mt][nt][e] = 0.0f;

    auto prefetch = [&](int c) {
        const uint32_t stg = base + (uint32_t)(c & 1) * STAGE_BYTES;
        const int koff = c * 64;
        // A tiles: 128 rows x 8 segs (1024 units / 256 thr = 4)
#pragma unroll
        for (int j = 0; j < 4; j++) {
            int idx = tid + 256 * j;
            int row = idx >> 3;
            int s   = idx & 7;
            uint32_t off = (uint32_t)(row * 128 + ((s ^ (row & 7)) << 4));
            size_t g = (size_t)row * EMB + koff + s * 8;
            cp16(stg + AH_OFF + off, Abh + g);
            cp16(stg + AL_OFF + off, Abl + g);
        }
        // B tiles: 96 rows x 8 segs (768 units / 256 thr = 3)
#pragma unroll
        for (int j = 0; j < 3; j++) {
            int idx = tid + 256 * j;
            int row = idx >> 3;
            int s   = idx & 7;
            uint32_t off = (uint32_t)(row * 128 + ((s ^ (row & 7)) << 4));
            size_t g = (size_t)row * EMB + koff + s * 8;
            cp16(stg + BH_OFF + off, Bbh + g);
            cp16(stg + BL_OFF + off, Bbl + g);
        }
    };

    prefetch(0);
    CP_COMMIT();

    const int qm = lane >> 3;
    const int r8 = lane & 7;

    for (int c = 0; c < NCHUNK; c++) {
        const uint32_t stg = base + (uint32_t)(c & 1) * STAGE_BYTES;

        if (c + 1 < NCHUNK) {
            prefetch(c + 1);
            CP_COMMIT();
            CP_WAIT(1);
        } else {
            CP_WAIT(0);
        }
        __syncthreads();

#pragma unroll
        for (int u = 0; u < 2; u++) {
            uint32_t ah[2][2][4], al[2][2][4];
#pragma unroll
            for (int mt = 0; mt < 2; mt++)
#pragma unroll
                for (int ks = 0; ks < 2; ks++) {
                    int arow = wm * 32 + mt * 16 + (qm & 1) * 8 + r8;
                    int aseg = (2 * u + ks) * 2 + (qm >> 1);
                    uint32_t sw = arow * 128 + ((aseg ^ (arow & 7)) << 4);
                    LDSM_X4(ah[mt][ks][0], ah[mt][ks][1], ah[mt][ks][2], ah[mt][ks][3],
                            stg + AH_OFF + sw);
                    LDSM_X4(al[mt][ks][0], al[mt][ks][1], al[mt][ks][2], al[mt][ks][3],
                            stg + AL_OFF + sw);
                }
#pragma unroll
            for (int nt = 0; nt < 6; nt++) {
                int brow = wn * 48 + nt * 8 + r8;
                int bseg = u * 4 + qm;
                uint32_t bsw = brow * 128 + ((bseg ^ (brow & 7)) << 4);
                uint32_t t0, t1, t2, t3;
                LDSM_X4(t0, t1, t2, t3, stg + BH_OFF + bsw);
#pragma unroll
                for (int mt = 0; mt < 2; mt++) {
                    mma16816(acc[mt][nt], ah[mt][0][0], ah[mt][0][1],
                             ah[mt][0][2], ah[mt][0][3], t0, t1);
                    mma16816(acc[mt][nt], ah[mt][1][0], ah[mt][1][1],
                             ah[mt][1][2], ah[mt][1][3], t2, t3);
                    mma16816(acc[mt][nt], al[mt][0][0], al[mt][0][1],
                             al[mt][0][2], al[mt][0][3], t0, t1);
                    mma16816(acc[mt][nt], al[mt][1][0], al[mt][1][1],
                             al[mt][1][2], al[mt][1][3], t2, t3);
                }
                LDSM_X4(t0, t1, t2, t3, stg + BL_OFF + bsw);
#pragma unroll
                for (int mt = 0; mt < 2; mt++) {
                    mma16816(acc[mt][nt], ah[mt][0][0], ah[mt][0][1],
                             ah[mt][0][2], ah[mt][0][3], t0, t1);
                    mma16816(acc[mt][nt], ah[mt][1][0], ah[mt][1][1],
                             ah[mt][1][2], ah[mt][1][3], t2, t3);
                }
            }
        }
        __syncthreads();
    }

    // ---- epilogue ----
    const int row0 = bm * 128 + wm * 32 + (lane >> 2);
    const int col0 = bn * 96 + wn * 48 + 2 * (lane & 3);
#pragma unroll
    for (int mt = 0; mt < 2; mt++)
#pragma unroll
        for (int nt = 0; nt < 6; nt++) {
            int rr = row0 + mt * 16;
            int cc = col0 + nt * 8;
            float b0 = bias[cc], b1 = bias[cc + 1];
            float v0 = acc[mt][nt][0] + b0, v1 = acc[mt][nt][1] + b1;
            float v2 = acc[mt][nt][2] + b0, v3 = acc[mt][nt][3] + b1;
            if (MODE == 0) {
                *(float2*)&C[(size_t)rr * N + cc]       = make_float2(v0, v1);
                *(float2*)&C[(size_t)(rr + 8) * N + cc] = make_float2(v2, v3);
            } else {
                int tensor = cc / 768;
                int within = cc % 768;
                int hh = within >> 6, dd = within & 63;
                if (tensor == 0) { v0 *= QSCALE; v1 *= QSCALE; v2 *= QSCALE; v3 *= QSCALE; }
                uint32_t h01, l01, h23, l23;
                split_pack(v0, v1, h01, l01);
                split_pack(v2, v3, h23, l23);
                {
                    int bb = rr >> 10, t = rr & 1023;
                    size_t di = (size_t)tensor * TSTRIDE +
                                (size_t)(bb * NH + hh) * (SEQ * HD) + (size_t)t * HD + dd;
                    *(uint32_t*)&outh[di] = h01;
                    *(uint32_t*)&outl[di] = l01;
                }
                {
                    int rr2 = rr + 8;
                    int bb = rr2 >> 10, t = rr2 & 1023;
                    size_t di = (size_t)tensor * TSTRIDE +
                                (size_t)(bb * NH + hh) * (SEQ * HD) + (size_t)t * HD + dd;
                    *(uint32_t*)&outh[di] = h23;
                    *(uint32_t*)&outl[di] = l23;
                }
            }
        }
}

// ---------------------------------------------------------------------------
// Tensor-core causal flash attention — 3-stage KV ring reusing Q smem.
// (unchanged from R12 — verified)
// ---------------------------------------------------------------------------
#define FT_BYTES  8192
#define FSTAGE    (4 * FT_BYTES)              // 32 KB: Kh,Kl,Vh,Vl
#define FLASH_SMEM (3 * FSTAGE + 1024)

__device__ __forceinline__ void prefetch_kv(uint32_t dst,
    const __nv_bfloat16* __restrict__ Kh, const __nv_bfloat16* __restrict__ Kl,
    const __nv_bfloat16* __restrict__ Vh, const __nv_bfloat16* __restrict__ Vl,
    int kt, int tid)
{
    const __nv_bfloat16* srcs[4] = {Kh, Kl, Vh, Vl};
#pragma unroll
    for (int t4 = 0; t4 < 4; t4++) {
        const __nv_bfloat16* src = srcs[t4] + (size_t)(kt * 64) * HD;
#pragma unroll
        for (int jj = 0; jj < 4; jj++) {
            int idx = tid + 128 * jj;
            int row = idx >> 3;
            int s   = idx & 7;
            cp16(dst + t4 * FT_BYTES + row * 128 + ((s ^ (row & 7)) << 4),
                 src + (size_t)row * HD + s * 8);
        }
    }
}

__global__ __launch_bounds__(128, 2) void flash_mma(
    const __nv_bfloat16* __restrict__ Sh, const __nv_bfloat16* __restrict__ Sl,
    __nv_bfloat16* __restrict__ ath, __nv_bfloat16* __restrict__ atl)
{
    extern __shared__ char sm_raw[];
    const uint32_t base = (smem_u32(sm_raw) + 1023) & ~1023u;

    const int tid  = threadIdx.x;
    const int lane = tid & 31;
    const int w    = tid >> 5;
    const int qm   = lane >> 3;
    const int r8   = lane & 7;
    const int tig  = lane & 3;
    const int gid  = lane >> 2;

    const int qt = (SEQ / 128 - 1) - blockIdx.x;   // heavy tiles first
    const int h  = blockIdx.y;
    const int b  = blockIdx.z;
    const int bh = b * NH + h;
    const int qbase = qt * 128;

    const size_t hb = (size_t)bh * (SEQ * HD);
    const __nv_bfloat16* Qhp = Sh + hb;
    const __nv_bfloat16* Qlp = Sl + hb;
    const __nv_bfloat16* Khp = Sh + TSTRIDE + hb;
    const __nv_bfloat16* Klp = Sl + TSTRIDE + hb;
    const __nv_bfloat16* Vhp = Sh + 2 * TSTRIDE + hb;
    const __nv_bfloat16* Vlp = Sl + 2 * TSTRIDE + hb;

    const int lastkt = 2 * qt + 1;

    const uint32_t QH_S = base + 2 * FSTAGE;
    const uint32_t QL_S = QH_S + 16384;

    {
        const __nv_bfloat16* qs[2] = {Qhp, Qlp};
        uint32_t qd[2] = {QH_S, QL_S};
#pragma unroll
        for (int t2 = 0; t2 < 2; t2++)
#pragma unroll
            for (int jj = 0; jj < 8; jj++) {
                int idx = tid + 128 * jj;
                int row = idx >> 3;
                int s   = idx & 7;
                cp16(qd[t2] + row * 128 + ((s ^ (row & 7)) << 4),
                     qs[t2] + (size_t)(qbase + row) * HD + s * 8);
            }
        CP_COMMIT();                                   // G_Q
        prefetch_kv(base, Khp, Klp, Vhp, Vlp, 0, tid);
        CP_COMMIT();                                   // G_0
        prefetch_kv(base + FSTAGE, Khp, Klp, Vhp, Vlp, 1, tid);
        CP_COMMIT();                                   // G_1
    }

    uint32_t qfh[2][4][4], qfl[2][4][4];
    CP_WAIT(2);
    __syncthreads();
#pragma unroll
    for (int mt = 0; mt < 2; mt++)
#pragma unroll
        for (int kk = 0; kk < 4; kk++) {
            int arow = w * 32 + mt * 16 + (qm & 1) * 8 + r8;
            int aseg = kk * 2 + (qm >> 1);
            uint32_t sw = ((aseg ^ (arow & 7)) << 4);
            LDSM_X4(qfh[mt][kk][0], qfh[mt][kk][1], qfh[mt][kk][2], qfh[mt][kk][3],
                    QH_S + arow * 128 + sw);
            LDSM_X4(qfl[mt][kk][0], qfl[mt][kk][1], qfl[mt][kk][2], qfl[mt][kk][3],
                    QL_S + arow * 128 + sw);
        }
    __syncthreads();

    float oacc[2][8][4];
#pragma unroll
    for (int mt = 0; mt < 2; mt++)
#pragma unroll
        for (int nt = 0; nt < 8; nt++)
#pragma unroll
            for (int e = 0; e < 4; e++) oacc[mt][nt][e] = 0.0f;
    float mrow[2][2], lrow[2][2];
#pragma unroll
    for (int mt = 0; mt < 2; mt++)
#pragma unroll
        for (int hf = 0; hf < 2; hf++) { mrow[mt][hf] = -1e30f; lrow[mt][hf] = 0.0f; }

    const int wrowmax = qbase + w * 32 + 31;

    for (int kt = 0; kt <= lastkt; kt++) {
        CP_WAIT(1);
        __syncthreads();
        if (kt + 2 <= lastkt)
            prefetch_kv(base + (uint32_t)((kt + 2) % 3) * FSTAGE,
                        Khp, Klp, Vhp, Vlp, kt + 2, tid);
        CP_COMMIT();

        const uint32_t SB = base + (uint32_t)(kt % 3) * FSTAGE;

        if (kt * 64 <= wrowmax) {
            const uint32_t sKh = SB;
            const uint32_t sKl = SB + FT_BYTES;
            const uint32_t sVh = SB + 2 * FT_BYTES;
            const uint32_t sVl = SB + 3 * FT_BYTES;

            float sacc[2][8][4];
#pragma unroll
            for (int mt = 0; mt < 2; mt++)
#pragma unroll
                for (int nt = 0; nt < 8; nt++)
#pragma unroll
                    for (int e = 0; e < 4; e++) sacc[mt][nt][e] = 0.0f;

#pragma unroll
            for (int u = 0; u < 2; u++)
#pragma unroll
                for (int nt = 0; nt < 8; nt++) {
                    int brow = nt * 8 + r8;
                    int bseg = u * 4 + qm;
                    uint32_t sw = ((bseg ^ (brow & 7)) << 4);
                    uint32_t t0, t1, t2, t3;
                    LDSM_X4(t0, t1, t2, t3, sKh + brow * 128 + sw);
#pragma unroll
                    for (int mt = 0; mt < 2; mt++) {
                        mma16816(sacc[mt][nt], qfh[mt][2 * u][0], qfh[mt][2 * u][1],
                                 qfh[mt][2 * u][2], qfh[mt][2 * u][3], t0, t1);
                        mma16816(sacc[mt][nt], qfh[mt][2 * u + 1][0], qfh[mt][2 * u + 1][1],
                                 qfh[mt][2 * u + 1][2], qfh[mt][2 * u + 1][3], t2, t3);
                        mma16816(sacc[mt][nt], qfl[mt][2 * u][0], qfl[mt][2 * u][1],
                                 qfl[mt][2 * u][2], qfl[mt][2 * u][3], t0, t1);
                        mma16816(sacc[mt][nt], qfl[mt][2 * u + 1][0], qfl[mt][2 * u + 1][1],
                                 qfl[mt][2 * u + 1][2], qfl[mt][2 * u + 1][3], t2, t3);
                    }
                    LDSM_X4(t0, t1, t2, t3, sKl + brow * 128 + sw);
#pragma unroll
                    for (int mt = 0; mt < 2; mt++) {
                        mma16816(sacc[mt][nt], qfh[mt][2 * u][0], qfh[mt][2 * u][1],
                                 qfh[mt][2 * u][2], qfh[mt][2 * u][3], t0, t1);
                        mma16816(sacc[mt][nt], qfh[mt][2 * u + 1][0], qfh[mt][2 * u + 1][1],
                                 qfh[mt][2 * u + 1][2], qfh[mt][2 * u + 1][3], t2, t3);
                    }
                }

            if (kt >= 2 * qt) {
                int qr0 = qbase + w * 32 + gid;
                int kc0 = kt * 64 + 2 * tig;
#pragma unroll
                for (int mt = 0; mt < 2; mt++)
#pragma unroll
                    for (int nt = 0; nt < 8; nt++)
#pragma unroll
                        for (int e = 0; e < 4; e++) {
                            int qr = qr0 + mt * 16 + (e >> 1) * 8;
                            int kc = kc0 + nt * 8 + (e & 1);
                            if (kc > qr) sacc[mt][nt][e] = -1e30f;
                        }
            }

            float corr[2][2], nm[2][2];
#pragma unroll
            for (int mt = 0; mt < 2; mt++)
#pragma unroll
                for (int hf = 0; hf < 2; hf++) {
                    float tm = -1e30f;
#pragma unroll
                    for (int nt = 0; nt < 8; nt++) {
                        tm = fmaxf(tm, sacc[mt][nt][2 * hf]);
                        tm = fmaxf(tm, sacc[mt][nt][2 * hf + 1]);
                    }
                    tm = fmaxf(tm, __shfl_xor_sync(0xffffffffu, tm, 1));
                    tm = fmaxf(tm, __shfl_xor_sync(0xffffffffu, tm, 2));
                    float n = fmaxf(mrow[mt][hf], tm);
                    corr[mt][hf] = ex2f(mrow[mt][hf] - n);
                    nm[mt][hf] = n;
                    mrow[mt][hf] = n;
                }

#pragma unroll
            for (int mt = 0; mt < 2; mt++)
#pragma unroll
                for (int hf = 0; hf < 2; hf++) {
                    float ps = 0.0f;
#pragma unroll
                    for (int nt = 0; nt < 8; nt++) {
                        float p0 = ex2f(sacc[mt][nt][2 * hf]     - nm[mt][hf]);
                        float p1 = ex2f(sacc[mt][nt][2 * hf + 1] - nm[mt][hf]);
                        sacc[mt][nt][2 * hf]     = p0;
                        sacc[mt][nt][2 * hf + 1] = p1;
                        ps += p0 + p1;
                    }
                    lrow[mt][hf] = lrow[mt][hf] * corr[mt][hf] + ps;
                }

#pragma unroll
            for (int mt = 0; mt < 2; mt++)
#pragma unroll
                for (int nt = 0; nt < 8; nt++) {
                    oacc[mt][nt][0] *= corr[mt][0];
                    oacc[mt][nt][1] *= corr[mt][0];
                    oacc[mt][nt][2] *= corr[mt][1];
                    oacc[mt][nt][3] *= corr[mt][1];
                }

            uint32_t pah[2][4][4], pal[2][4][4];
#pragma unroll
            for (int mt = 0; mt < 2; mt++)
#pragma unroll
                for (int j = 0; j < 4; j++) {
                    split_pack(sacc[mt][2 * j][0],     sacc[mt][2 * j][1],
                               pah[mt][j][0], pal[mt][j][0]);
                    split_pack(sacc[mt][2 * j][2],     sacc[mt][2 * j][3],
                               pah[mt][j][1], pal[mt][j][1]);
                    split_pack(sacc[mt][2 * j + 1][0], sacc[mt][2 * j + 1][1],
                               pah[mt][j][2], pal[mt][j][2]);
                    split_pack(sacc[mt][2 * j + 1][2], sacc[mt][2 * j + 1][3],
                               pah[mt][j][3], pal[mt][j][3]);
                }

#pragma unroll
            for (int j = 0; j < 4; j++)
#pragma unroll
                for (int dp = 0; dp < 4; dp++) {
                    int rowv = j * 16 + (lane & 15);
                    int segv = dp * 2 + (lane >> 4);
                    uint32_t sw = ((segv ^ (rowv & 7)) << 4);
                    uint32_t t0, t1, t2, t3;
                    LDSM_X4T(t0, t1, t2, t3, sVh + rowv * 128 + sw);
#pragma unroll
                    for (int mt = 0; mt < 2; mt++) {
                        mma16816(oacc[mt][2 * dp], pah[mt][j][0], pah[mt][j][1],
                                 pah[mt][j][2], pah[mt][j][3], t0, t1);
                        mma16816(oacc[mt][2 * dp + 1], pah[mt][j][0], pah[mt][j][1],
                                 pah[mt][j][2], pah[mt][j][3], t2, t3);
                        mma16816(oacc[mt][2 * dp], pal[mt][j][0], pal[mt][j][1],
                                 pal[mt][j][2], pal[mt][j][3], t0, t1);
                        mma16816(oacc[mt][2 * dp + 1], pal[mt][j][0], pal[mt][j][1],
                                 pal[mt][j][2], pal[mt][j][3], t2, t3);
                    }
                    LDSM_X4T(t0, t1, t2, t3, sVl + rowv * 128 + sw);
#pragma unroll
                    for (int mt = 0; mt < 2; mt++) {
                        mma16816(oacc[mt][2 * dp], pah[mt][j][0], pah[mt][j][1],
                                 pah[mt][j][2], pah[mt][j][3], t0, t1);
                        mma16816(oacc[mt][2 * dp + 1], pah[mt][j][0], pah[mt][j][1],
                                 pah[mt][j][2], pah[mt][j][3], t2, t3);
                    }
                }
        }
    }

    float inv[2][2];
#pragma unroll
    for (int mt = 0; mt < 2; mt++)
#pragma unroll
        for (int hf = 0; hf < 2; hf++) {
            float lv = lrow[mt][hf];
            lv += __shfl_xor_sync(0xffffffffu, lv, 1);
            lv += __shfl_xor_sync(0xffffffffu, lv, 2);
            inv[mt][hf] = 1.0f / lv;
        }

#pragma unroll
    for (int mt = 0; mt < 2; mt++)
#pragma unroll
        for (int nt = 0; nt < 8; nt++) {
            int t0r = qbase + w * 32 + mt * 16 + gid;
            int col = h * HD + nt * 8 + 2 * tig;
            {
                float v0 = oacc[mt][nt][0] * inv[mt][0];
                float v1 = oacc[mt][nt][1] * inv[mt][0];
                uint32_t hp, lp;
                split_pack(v0, v1, hp, lp);
                size_t di = (size_t)(b * SEQ + t0r) * EMB + col;
                *(uint32_t*)&ath[di] = hp;
                *(uint32_t*)&atl[di] = lp;
            }
            {
                float v2 = oacc[mt][nt][2] * inv[mt][1];
                float v3 = oacc[mt][nt][3] * inv[mt][1];
                uint32_t hp, lp;
                split_pack(v2, v3, hp, lp);
                size_t di = (size_t)(b * SEQ + t0r + 8) * EMB + col;
                *(uint32_t*)&ath[di] = hp;
                *(uint32_t*)&atl[di] = lp;
            }
        }
}

// ---------------------------------------------------------------------------
extern "C" void kernel_launch(void* const* d_in, const int* in_sizes, int n_in,
                              void* d_out, int out_size)
{
    (void)in_sizes; (void)n_in; (void)out_size;
    const float* x      = (const float*)d_in[0];
    const float* W_attn = (const float*)d_in[1];
    const float* b_attn = (const float*)d_in[2];
    const float* W_proj = (const float*)d_in[3];
    const float* b_proj = (const float*)d_in[4];
    float* out = (float*)d_out;

    __nv_bfloat16 *ah, *al, *wath, *watl, *wpth, *wptl, *sh, *sl;
    cudaGetSymbolAddress((void**)&ah, g_Ah);
    cudaGetSymbolAddress((void**)&al, g_Al);
    cudaGetSymbolAddress((void**)&wath, g_WaTh);
    cudaGetSymbolAddress((void**)&watl, g_WaTl);
    cudaGetSymbolAddress((void**)&wpth, g_WpTh);
    cudaGetSymbolAddress((void**)&wptl, g_WpTl);
    cudaGetSymbolAddress((void**)&sh, g_Sh);
    cudaGetSymbolAddress((void**)&sl, g_Sl);

    cudaFuncSetAttribute(gemm_mma<0>, cudaFuncAttributeMaxDynamicSharedMemorySize, GEMM_SMEM);
    cudaFuncSetAttribute(gemm_mma<1>, cudaFuncAttributeMaxDynamicSharedMemorySize, GEMM_SMEM);
    cudaFuncSetAttribute(flash_mma,  cudaFuncAttributeMaxDynamicSharedMemorySize, FLASH_SMEM);

    {
        int n = MROWS * EMB;
        split2<<<(n + 255) / 256, 256>>>(x, ah, al, n);
    }
    transpose_split<<<dim3(QKVN / 32, EMB / 32), dim3(32, 8)>>>(W_attn, wath, watl, EMB, QKVN);
    transpose_split<<<dim3(EMB / 32, EMB / 32), dim3(32, 8)>>>(W_proj, wpth, wptl, EMB, EMB);

    // 1) QKV GEMM -> split bf16, head-major, q pre-scaled
    gemm_mma<1><<<dim3(QKVN / 96, MROWS / 128), 256, GEMM_SMEM>>>(
        ah, al, wath, watl, b_attn, nullptr, QKVN, sh, sl);

    // 2) tensor-core causal flash attention -> att split (reuses ah/al)
    flash_mma<<<dim3(SEQ / 128, NH, BATCH), 128, FLASH_SMEM>>>(sh, sl, ah, al);

    // 3) projection GEMM -> out fp32
    gemm_mma<0><<<dim3(EMB / 96, MROWS / 128), 256, GEMM_SMEM>>>(
        ah, al, wpth, wptl, b_proj, out, EMB, nullptr, nullptr);
}

// round 15
// speedup vs baseline: 1.3987x; 1.3987x over previous
#include <cuda_runtime.h>
#include <cuda_fp16.h>
#include <cstdint>
#include <math.h>

#define EMB   768
#define NH    12
#define HD    64
#define BATCH 8
#define SEQ   1024
#define MROWS (BATCH * SEQ)      // 8192
#define QKVN  (3 * EMB)          // 2304

// 0.125 (1/sqrt(64)) * log2(e): folded into Q so softmax uses ex2
#define QSCALE 0.18033688011112042f

#define TSTRIDE ((size_t)BATCH * NH * SEQ * HD)   // elems per q/k/v tensor

// ---------------------------------------------------------------------------
// Scratch (no allocations allowed) — fp16 planes
// ---------------------------------------------------------------------------
__device__ __align__(256) __half g_Ah[(size_t)MROWS * EMB];
__device__ __align__(256) __half g_Al[(size_t)MROWS * EMB];
__device__ __align__(256) __half g_WaTh[(size_t)QKVN * EMB];
__device__ __align__(256) __half g_WpTh[(size_t)EMB * EMB];
__device__ __align__(256) __half g_Sh[3 * TSTRIDE];
__device__ __align__(256) __half g_Sl[3 * TSTRIDE];    // only q-plane's lo is consumed

// ---------------------------------------------------------------------------
// PTX helpers (sm_80-class only; toolchain targets plain sm_103)
// ---------------------------------------------------------------------------
__device__ __forceinline__ uint32_t smem_u32(const void* p) {
    uint32_t a;
    asm("{ .reg .u64 t; cvta.to.shared.u64 t, %1; cvt.u32.u64 %0, t; }"
        : "=r"(a) : "l"(p));
    return a;
}
__device__ __forceinline__ void cp16(uint32_t dst, const void* src) {
    asm volatile("cp.async.cg.shared.global [%0], [%1], 16;"
                 :: "r"(dst), "l"(src) : "memory");
}
#define CP_COMMIT() asm volatile("cp.async.commit_group;" ::: "memory")
#define CP_WAIT(n)  asm volatile("cp.async.wait_group %0;" :: "n"(n) : "memory")

#define LDSM_X4(r0, r1, r2, r3, addr) \
    asm volatile("ldmatrix.sync.aligned.m8n8.x4.shared.b16 {%0,%1,%2,%3}, [%4];" \
                 : "=r"(r0), "=r"(r1), "=r"(r2), "=r"(r3) : "r"(addr))
#define LDSM_X4T(r0, r1, r2, r3, addr) \
    asm volatile("ldmatrix.sync.aligned.m8n8.x4.trans.shared.b16 {%0,%1,%2,%3}, [%4];" \
                 : "=r"(r0), "=r"(r1), "=r"(r2), "=r"(r3) : "r"(addr))

// fp16 inputs, fp32 accumulate
__device__ __forceinline__ void mma16816(float* d,
                                         uint32_t a0, uint32_t a1, uint32_t a2, uint32_t a3,
                                         uint32_t b0, uint32_t b1) {
    asm volatile("mma.sync.aligned.m16n8k16.row.col.f32.f16.f16.f32 "
                 "{%0,%1,%2,%3}, {%4,%5,%6,%7}, {%8,%9}, {%0,%1,%2,%3};"
                 : "+f"(d[0]), "+f"(d[1]), "+f"(d[2]), "+f"(d[3])
                 : "r"(a0), "r"(a1), "r"(a2), "r"(a3), "r"(b0), "r"(b1));
}

__device__ __forceinline__ float ex2f(float x) {
    float y;
    asm("ex2.approx.ftz.f32 %0, %1;" : "=f"(y) : "f"(x));
    return y;
}

// Exact fp16 split: hi = f16x2(p0,p1); residuals via cvt back + subtract.
__device__ __forceinline__ void split_pack(float p0, float p1, uint32_t& hi, uint32_t& lo) {
    uint32_t h;
    asm("cvt.rn.f16x2.f32 %0, %1, %2;" : "=r"(h) : "f"(p1), "f"(p0));  // low=p0
    float f0, f1;
    asm("{.reg .b16 a,b; mov.b32 {a,b}, %2; cvt.f32.f16 %0, a; cvt.f32.f16 %1, b;}"
        : "=f"(f0), "=f"(f1) : "r"(h));
    float r0 = p0 - f0;
    float r1 = p1 - f1;
    uint32_t l;
    asm("cvt.rn.f16x2.f32 %0, %1, %2;" : "=r"(l) : "f"(r1), "f"(r0));
    hi = h; lo = l;
}

// ---------------------------------------------------------------------------
// Prologue kernels
// ---------------------------------------------------------------------------
__global__ __launch_bounds__(256) void split2(const float* __restrict__ src,
                                              __half* __restrict__ hi,
                                              __half* __restrict__ lo, int n)
{
    int i = blockIdx.x * blockDim.x + threadIdx.x;
    if (i < n) {
        float v = src[i];
        __half h = __float2half_rn(v);
        hi[i] = h;
        lo[i] = __float2half_rn(v - __half2float(h));
    }
}

// Transpose: W [K,N] fp32 -> Th [N,K] fp16 (hi only; residual dropped by design)
__global__ __launch_bounds__(256) void transpose_hi(
    const float* __restrict__ W, __half* __restrict__ Th, int K, int N)
{
    __shared__ float t[32][33];
    int k0 = blockIdx.y * 32, n0 = blockIdx.x * 32;
#pragma unroll
    for (int r = 0; r < 32; r += 8) {
        int k = k0 + threadIdx.y + r;
        int n = n0 + threadIdx.x;
        t[threadIdx.y + r][threadIdx.x] = W[(size_t)k * N + n];
    }
    __syncthreads();
#pragma unroll
    for (int r = 0; r < 32; r += 8) {
        int n = n0 + threadIdx.y + r;
        int k = k0 + threadIdx.x;
        Th[(size_t)n * K + k] = __float2half_rn(t[threadIdx.x][threadIdx.y + r]);
    }
}

// ---------------------------------------------------------------------------
// fp16 2-term mma.sync GEMM: C ~= AhBh + AlBh = A @ Bh^T (+bias), fp32 accum.
// CTA tile 128x96, 128 threads, 4 warps (2M x 2N), warp tile 64x48 (R12 shape).
// Stage: Ah 16K + Al 16K + Bh 12K = 44 KB; 2 stages = 88 KB -> 2 CTAs/SM.
// MODE 0: fp32 out + bias.  MODE 1: qkv epilogue (split + head-major scatter).
// ---------------------------------------------------------------------------
#define AH_OFF      0
#define AL_OFF      16384
#define BH_OFF      32768
#define STAGE_BYTES 45056
#define GEMM_SMEM   (2 * STAGE_BYTES + 256)
#define NCHUNK      12

template <int MODE>
__global__ __launch_bounds__(128, 2) void gemm_mma(
    const __half* __restrict__ Ah, const __half* __restrict__ Al,
    const __half* __restrict__ Bh,
    const float* __restrict__ bias, float* __restrict__ C, int N,
    __half* __restrict__ outh, __half* __restrict__ outl)
{
    extern __shared__ char sm_raw[];
    const uint32_t base = (smem_u32(sm_raw) + 127) & ~127u;

    const int tid  = threadIdx.x;
    const int lane = tid & 31;
    const int w    = tid >> 5;
    const int wm   = w & 1;               // 64-row slice
    const int wn   = w >> 1;              // 48-col slice
    const int bn   = blockIdx.x;
    const int bm   = blockIdx.y;

    const __half* Abh = Ah + (size_t)bm * 128 * EMB;
    const __half* Abl = Al + (size_t)bm * 128 * EMB;
    const __half* Bbh = Bh + (size_t)bn * 96 * EMB;

    float acc[4][6][4];
#pragma unroll
    for (int mt = 0; mt < 4; mt++)
#pragma unroll
        for (int nt = 0; nt < 6; nt++)
#pragma unroll
            for (int e = 0; e < 4; e++) acc[mt][nt][e] = 0.0f;

    auto prefetch = [&](int c) {
        const uint32_t stg = base + (uint32_t)(c & 1) * STAGE_BYTES;
        const int koff = c * 64;
#pragma unroll
        for (int j = 0; j < 8; j++) {
            int idx = tid + 128 * j;          // 0..1023
            int row = idx >> 3;
            int s   = idx & 7;
            uint32_t off = (uint32_t)(row * 128 + ((s ^ (row & 7)) << 4));
            size_t g = (size_t)row * EMB + koff + s * 8;
            cp16(stg + AH_OFF + off, Abh + g);
            cp16(stg + AL_OFF + off, Abl + g);
        }
#pragma unroll
        for (int j = 0; j < 6; j++) {
            int idx = tid + 128 * j;          // 0..767
            int row = idx >> 3;
            int s   = idx & 7;
            uint32_t off = (uint32_t)(row * 128 + ((s ^ (row & 7)) << 4));
            cp16(stg + BH_OFF + off, Bbh + (size_t)row * EMB + koff + s * 8);
        }
    };

    prefetch(0);
    CP_COMMIT();

    const int qm = lane >> 3;
    const int r8 = lane & 7;

    for (int c = 0; c < NCHUNK; c++) {
        const uint32_t stg = base + (uint32_t)(c & 1) * STAGE_BYTES;

        if (c + 1 < NCHUNK) {
            prefetch(c + 1);
            CP_COMMIT();
            CP_WAIT(1);
        } else {
            CP_WAIT(0);
        }
        __syncthreads();

#pragma unroll
        for (int u = 0; u < 2; u++) {
            uint32_t ah[4][2][4], al[4][2][4];
#pragma unroll
            for (int mt = 0; mt < 4; mt++)
#pragma unroll
                for (int ks = 0; ks < 2; ks++) {
                    int arow = wm * 64 + mt * 16 + (qm & 1) * 8 + r8;
                    int aseg = (2 * u + ks) * 2 + (qm >> 1);
                    uint32_t sw = arow * 128 + ((aseg ^ (arow & 7)) << 4);
                    LDSM_X4(ah[mt][ks][0], ah[mt][ks][1], ah[mt][ks][2], ah[mt][ks][3],
                            stg + AH_OFF + sw);
                    LDSM_X4(al[mt][ks][0], al[mt][ks][1], al[mt][ks][2], al[mt][ks][3],
                            stg + AL_OFF + sw);
                }
#pragma unroll
            for (int nt = 0; nt < 6; nt++) {
                int brow = wn * 48 + nt * 8 + r8;
                int bseg = u * 4 + qm;
                uint32_t t0, t1, t2, t3;
                LDSM_X4(t0, t1, t2, t3,
                        stg + BH_OFF + brow * 128 + ((bseg ^ (brow & 7)) << 4));
#pragma unroll
                for (int mt = 0; mt < 4; mt++) {
                    mma16816(acc[mt][nt], ah[mt][0][0], ah[mt][0][1],
                             ah[mt][0][2], ah[mt][0][3], t0, t1);
                    mma16816(acc[mt][nt], ah[mt][1][0], ah[mt][1][1],
                             ah[mt][1][2], ah[mt][1][3], t2, t3);
                    mma16816(acc[mt][nt], al[mt][0][0], al[mt][0][1],
                             al[mt][0][2], al[mt][0][3], t0, t1);
                    mma16816(acc[mt][nt], al[mt][1][0], al[mt][1][1],
                             al[mt][1][2], al[mt][1][3], t2, t3);
                }
            }
        }
        __syncthreads();
    }

    // ---- epilogue ----
    const int row0 = bm * 128 + wm * 64 + (lane >> 2);
    const int col0 = bn * 96 + wn * 48 + 2 * (lane & 3);
#pragma unroll
    for (int mt = 0; mt < 4; mt++)
#pragma unroll
        for (int nt = 0; nt < 6; nt++) {
            int rr = row0 + mt * 16;
            int cc = col0 + nt * 8;
            float b0 = bias[cc], b1 = bias[cc + 1];
            float v0 = acc[mt][nt][0] + b0, v1 = acc[mt][nt][1] + b1;
            float v2 = acc[mt][nt][2] + b0, v3 = acc[mt][nt][3] + b1;
            if (MODE == 0) {
                *(float2*)&C[(size_t)rr * N + cc]       = make_float2(v0, v1);
                *(float2*)&C[(size_t)(rr + 8) * N + cc] = make_float2(v2, v3);
            } else {
                int tensor = cc / 768;
                int within = cc % 768;
                int hh = within >> 6, dd = within & 63;
                if (tensor == 0) { v0 *= QSCALE; v1 *= QSCALE; v2 *= QSCALE; v3 *= QSCALE; }
                uint32_t h01, l01, h23, l23;
                split_pack(v0, v1, h01, l01);
                split_pack(v2, v3, h23, l23);
                {
                    int bb = rr >> 10, t = rr & 1023;
                    size_t di = (size_t)tensor * TSTRIDE +
                                (size_t)(bb * NH + hh) * (SEQ * HD) + (size_t)t * HD + dd;
                    *(uint32_t*)&outh[di] = h01;
                    if (tensor == 0) *(uint32_t*)&outl[di] = l01;   // lo consumed only for Q
                }
                {
                    int rr2 = rr + 8;
                    int bb = rr2 >> 10, t = rr2 & 1023;
                    size_t di = (size_t)tensor * TSTRIDE +
                                (size_t)(bb * NH + hh) * (SEQ * HD) + (size_t)t * HD + dd;
                    *(uint32_t*)&outh[di] = h23;
                    if (tensor == 0) *(uint32_t*)&outl[di] = l23;
                }
            }
        }
}

// ---------------------------------------------------------------------------
// fp16 2-term causal flash attention — 3-stage KV ring (Kh+Vh only, 16 KB/slot)
// + separate Q (hi/lo, 32 KB). S = (Qh+Ql)·Kh^T; O += (Ph+Pl)·Vh.
// ---------------------------------------------------------------------------
#define FT_BYTES   8192
#define FSTAGE_F   (2 * FT_BYTES)             // Kh, Vh
#define FQ_OFF     (3 * FSTAGE_F)             // 49152
#define FLASH_SMEM (FQ_OFF + 32768 + 1024)

__device__ __forceinline__ void prefetch_kv(uint32_t dst,
    const __half* __restrict__ Kh, const __half* __restrict__ Vh,
    int kt, int tid)
{
    const __half* srcs[2] = {Kh, Vh};
#pragma unroll
    for (int t2 = 0; t2 < 2; t2++) {
        const __half* src = srcs[t2] + (size_t)(kt * 64) * HD;
#pragma unroll
        for (int jj = 0; jj < 4; jj++) {
            int idx = tid + 128 * jj;
            int row = idx >> 3;
            int s   = idx & 7;
            cp16(dst + t2 * FT_BYTES + row * 128 + ((s ^ (row & 7)) << 4),
                 src + (size_t)row * HD + s * 8);
        }
    }
}

__global__ __launch_bounds__(128, 2) void flash_mma(
    const __half* __restrict__ Sh, const __half* __restrict__ Sl,
    __half* __restrict__ ath, __half* __restrict__ atl)
{
    extern __shared__ char sm_raw[];
    const uint32_t base = (smem_u32(sm_raw) + 1023) & ~1023u;

    const int tid  = threadIdx.x;
    const int lane = tid & 31;
    const int w    = tid >> 5;
    const int qm   = lane >> 3;
    const int r8   = lane & 7;
    const int tig  = lane & 3;
    const int gid  = lane >> 2;

    const int qt = (SEQ / 128 - 1) - blockIdx.x;   // heavy tiles first
    const int h  = blockIdx.y;
    const int b  = blockIdx.z;
    const int bh = b * NH + h;
    const int qbase = qt * 128;

    const size_t hb = (size_t)bh * (SEQ * HD);
    const __half* Qhp = Sh + hb;
    const __half* Qlp = Sl + hb;
    const __half* Khp = Sh + TSTRIDE + hb;
    const __half* Vhp = Sh + 2 * TSTRIDE + hb;

    const int lastkt = 2 * qt + 1;

    const uint32_t QH_S = base + FQ_OFF;
    const uint32_t QL_S = QH_S + 16384;

    // --- prologue groups: G_Q, G_0, G_1 ---
    {
        const __half* qs[2] = {Qhp, Qlp};
        uint32_t qd[2] = {QH_S, QL_S};
#pragma unroll
        for (int t2 = 0; t2 < 2; t2++)
#pragma unroll
            for (int jj = 0; jj < 8; jj++) {
                int idx = tid + 128 * jj;
                int row = idx >> 3;
                int s   = idx & 7;
                cp16(qd[t2] + row * 128 + ((s ^ (row & 7)) << 4),
                     qs[t2] + (size_t)(qbase + row) * HD + s * 8);
            }
        CP_COMMIT();                                   // G_Q
        prefetch_kv(base, Khp, Vhp, 0, tid);
        CP_COMMIT();                                   // G_0
        prefetch_kv(base + FSTAGE_F, Khp, Vhp, 1, tid);
        CP_COMMIT();                                   // G_1
    }

    uint32_t qfh[2][4][4], qfl[2][4][4];
    CP_WAIT(2);
    __syncthreads();
#pragma unroll
    for (int mt = 0; mt < 2; mt++)
#pragma unroll
        for (int kk = 0; kk < 4; kk++) {
            int arow = w * 32 + mt * 16 + (qm & 1) * 8 + r8;
            int aseg = kk * 2 + (qm >> 1);
            uint32_t sw = ((aseg ^ (arow & 7)) << 4);
            LDSM_X4(qfh[mt][kk][0], qfh[mt][kk][1], qfh[mt][kk][2], qfh[mt][kk][3],
                    QH_S + arow * 128 + sw);
            LDSM_X4(qfl[mt][kk][0], qfl[mt][kk][1], qfl[mt][kk][2], qfl[mt][kk][3],
                    QL_S + arow * 128 + sw);
        }

    float oacc[2][8][4];
#pragma unroll
    for (int mt = 0; mt < 2; mt++)
#pragma unroll
        for (int nt = 0; nt < 8; nt++)
#pragma unroll
            for (int e = 0; e < 4; e++) oacc[mt][nt][e] = 0.0f;
    float mrow[2][2], lrow[2][2];
#pragma unroll
    for (int mt = 0; mt < 2; mt++)
#pragma unroll
        for (int hf = 0; hf < 2; hf++) { mrow[mt][hf] = -1e30f; lrow[mt][hf] = 0.0f; }

    const int wrowmax = qbase + w * 32 + 31;

    for (int kt = 0; kt <= lastkt; kt++) {
        CP_WAIT(1);
        __syncthreads();
        if (kt + 2 <= lastkt)
            prefetch_kv(base + (uint32_t)((kt + 2) % 3) * FSTAGE_F,
                        Khp, Vhp, kt + 2, tid);
        CP_COMMIT();

        const uint32_t SB = base + (uint32_t)(kt % 3) * FSTAGE_F;

        if (kt * 64 <= wrowmax) {
            const uint32_t sKh = SB;
            const uint32_t sVh = SB + FT_BYTES;

            float sacc[2][8][4];
#pragma unroll
            for (int mt = 0; mt < 2; mt++)
#pragma unroll
                for (int nt = 0; nt < 8; nt++)
#pragma unroll
                    for (int e = 0; e < 4; e++) sacc[mt][nt][e] = 0.0f;

#pragma unroll
            for (int u = 0; u < 2; u++)
#pragma unroll
                for (int nt = 0; nt < 8; nt++) {
                    int brow = nt * 8 + r8;
                    int bseg = u * 4 + qm;
                    uint32_t sw = ((bseg ^ (brow & 7)) << 4);
                    uint32_t t0, t1, t2, t3;
                    LDSM_X4(t0, t1, t2, t3, sKh + brow * 128 + sw);
#pragma unroll
                    for (int mt = 0; mt < 2; mt++) {
                        mma16816(sacc[mt][nt], qfh[mt][2 * u][0], qfh[mt][2 * u][1],
                                 qfh[mt][2 * u][2], qfh[mt][2 * u][3], t0, t1);
                        mma16816(sacc[mt][nt], qfh[mt][2 * u + 1][0], qfh[mt][2 * u + 1][1],
                                 qfh[mt][2 * u + 1][2], qfh[mt][2 * u + 1][3], t2, t3);
                        mma16816(sacc[mt][nt], qfl[mt][2 * u][0], qfl[mt][2 * u][1],
                                 qfl[mt][2 * u][2], qfl[mt][2 * u][3], t0, t1);
                        mma16816(sacc[mt][nt], qfl[mt][2 * u + 1][0], qfl[mt][2 * u + 1][1],
                                 qfl[mt][2 * u + 1][2], qfl[mt][2 * u + 1][3], t2, t3);
                    }
                }

            if (kt >= 2 * qt) {
                int qr0 = qbase + w * 32 + gid;
                int kc0 = kt * 64 + 2 * tig;
#pragma unroll
                for (int mt = 0; mt < 2; mt++)
#pragma unroll
                    for (int nt = 0; nt < 8; nt++)
#pragma unroll
                        for (int e = 0; e < 4; e++) {
                            int qr = qr0 + mt * 16 + (e >> 1) * 8;
                            int kc = kc0 + nt * 8 + (e & 1);
                            if (kc > qr) sacc[mt][nt][e] = -1e30f;
                        }
            }

            float corr[2][2], nm[2][2];
#pragma unroll
            for (int mt = 0; mt < 2; mt++)
#pragma unroll
                for (int hf = 0; hf < 2; hf++) {
                    float tm = -1e30f;
#pragma unroll
                    for (int nt = 0; nt < 8; nt++) {
                        tm = fmaxf(tm, sacc[mt][nt][2 * hf]);
                        tm = fmaxf(tm, sacc[mt][nt][2 * hf + 1]);
                    }
                    tm = fmaxf(tm, __shfl_xor_sync(0xffffffffu, tm, 1));
                    tm = fmaxf(tm, __shfl_xor_sync(0xffffffffu, tm, 2));
                    float n = fmaxf(mrow[mt][hf], tm);
                    corr[mt][hf] = ex2f(mrow[mt][hf] - n);
                    nm[mt][hf] = n;
                    mrow[mt][hf] = n;
                }

#pragma unroll
            for (int mt = 0; mt < 2; mt++)
#pragma unroll
                for (int hf = 0; hf < 2; hf++) {
                    float ps = 0.0f;
#pragma unroll
                    for (int nt = 0; nt < 8; nt++) {
                        float p0 = ex2f(sacc[mt][nt][2 * hf]     - nm[mt][hf]);
                        float p1 = ex2f(sacc[mt][nt][2 * hf + 1] - nm[mt][hf]);
                        sacc[mt][nt][2 * hf]     = p0;
                        sacc[mt][nt][2 * hf + 1] = p1;
                        ps += p0 + p1;
                    }
                    lrow[mt][hf] = lrow[mt][hf] * corr[mt][hf] + ps;
                }

#pragma unroll
            for (int mt = 0; mt < 2; mt++)
#pragma unroll
                for (int nt = 0; nt < 8; nt++) {
                    oacc[mt][nt][0] *= corr[mt][0];
                    oacc[mt][nt][1] *= corr[mt][0];
                    oacc[mt][nt][2] *= corr[mt][1];
                    oacc[mt][nt][3] *= corr[mt][1];
                }

            uint32_t pah[2][4][4], pal[2][4][4];
#pragma unroll
            for (int mt = 0; mt < 2; mt++)
#pragma unroll
                for (int j = 0; j < 4; j++) {
                    split_pack(sacc[mt][2 * j][0],     sacc[mt][2 * j][1],
                               pah[mt][j][0], pal[mt][j][0]);
                    split_pack(sacc[mt][2 * j][2],     sacc[mt][2 * j][3],
                               pah[mt][j][1], pal[mt][j][1]);
                    split_pack(sacc[mt][2 * j + 1][0], sacc[mt][2 * j + 1][1],
                               pah[mt][j][2], pal[mt][j][2]);
                    split_pack(sacc[mt][2 * j + 1][2], sacc[mt][2 * j + 1][3],
                               pah[mt][j][3], pal[mt][j][3]);
                }

#pragma unroll
            for (int j = 0; j < 4; j++)
#pragma unroll
                for (int dp = 0; dp < 4; dp++) {
                    int rowv = j * 16 + (lane & 15);
                    int segv = dp * 2 + (lane >> 4);
                    uint32_t sw = ((segv ^ (rowv & 7)) << 4);
                    uint32_t t0, t1, t2, t3;
                    LDSM_X4T(t0, t1, t2, t3, sVh + rowv * 128 + sw);
#pragma unroll
                    for (int mt = 0; mt < 2; mt++) {
                        mma16816(oacc[mt][2 * dp], pah[mt][j][0], pah[mt][j][1],
                                 pah[mt][j][2], pah[mt][j][3], t0, t1);
                        mma16816(oacc[mt][2 * dp + 1], pah[mt][j][0], pah[mt][j][1],
                                 pah[mt][j][2], pah[mt][j][3], t2, t3);
                        mma16816(oacc[mt][2 * dp], pal[mt][j][0], pal[mt][j][1],
                                 pal[mt][j][2], pal[mt][j][3], t0, t1);
                        mma16816(oacc[mt][2 * dp + 1], pal[mt][j][0], pal[mt][j][1],
                                 pal[mt][j][2], pal[mt][j][3], t2, t3);
                    }
                }
        }
    }

    float inv[2][2];
#pragma unroll
    for (int mt = 0; mt < 2; mt++)
#pragma unroll
        for (int hf = 0; hf < 2; hf++) {
            float lv = lrow[mt][hf];
            lv += __shfl_xor_sync(0xffffffffu, lv, 1);
            lv += __shfl_xor_sync(0xffffffffu, lv, 2);
            inv[mt][hf] = 1.0f / lv;
        }

#pragma unroll
    for (int mt = 0; mt < 2; mt++)
#pragma unroll
        for (int nt = 0; nt < 8; nt++) {
            int t0r = qbase + w * 32 + mt * 16 + gid;
            int col = h * HD + nt * 8 + 2 * tig;
            {
                float v0 = oacc[mt][nt][0] * inv[mt][0];
                float v1 = oacc[mt][nt][1] * inv[mt][0];
                uint32_t hp, lp;
                split_pack(v0, v1, hp, lp);
                size_t di = (size_t)(b * SEQ + t0r) * EMB + col;
                *(uint32_t*)&ath[di] = hp;
                *(uint32_t*)&atl[di] = lp;
            }
            {
                float v2 = oacc[mt][nt][2] * inv[mt][1];
                float v3 = oacc[mt][nt][3] * inv[mt][1];
                uint32_t hp, lp;
                split_pack(v2, v3, hp, lp);
                size_t di = (size_t)(b * SEQ + t0r + 8) * EMB + col;
                *(uint32_t*)&ath[di] = hp;
                *(uint32_t*)&atl[di] = lp;
            }
        }
}

// ---------------------------------------------------------------------------
extern "C" void kernel_launch(void* const* d_in, const int* in_sizes, int n_in,
                              void* d_out, int out_size)
{
    (void)in_sizes; (void)n_in; (void)out_size;
    const float* x      = (const float*)d_in[0];
    const float* W_attn = (const float*)d_in[1];
    const float* b_attn = (const float*)d_in[2];
    const float* W_proj = (const float*)d_in[3];
    const float* b_proj = (const float*)d_in[4];
    float* out = (float*)d_out;

    __half *ah, *al, *wath, *wpth, *sh, *sl;
    cudaGetSymbolAddress((void**)&ah, g_Ah);
    cudaGetSymbolAddress((void**)&al, g_Al);
    cudaGetSymbolAddress((void**)&wath, g_WaTh);
    cudaGetSymbolAddress((void**)&wpth, g_WpTh);
    cudaGetSymbolAddress((void**)&sh, g_Sh);
    cudaGetSymbolAddress((void**)&sl, g_Sl);

    cudaFuncSetAttribute(gemm_mma<0>, cudaFuncAttributeMaxDynamicSharedMemorySize, GEMM_SMEM);
    cudaFuncSetAttribute(gemm_mma<1>, cudaFuncAttributeMaxDynamicSharedMemorySize, GEMM_SMEM);
    cudaFuncSetAttribute(flash_mma,  cudaFuncAttributeMaxDynamicSharedMemorySize, FLASH_SMEM);

    // Prologue: split x (hi+lo fp16); transpose weights (hi only)
    {
        int n = MROWS * EMB;
        split2<<<(n + 255) / 256, 256>>>(x, ah, al, n);
    }
    transpose_hi<<<dim3(QKVN / 32, EMB / 32), dim3(32, 8)>>>(W_attn, wath, EMB, QKVN);
    transpose_hi<<<dim3(EMB / 32, EMB / 32), dim3(32, 8)>>>(W_proj, wpth, EMB, EMB);

    // 1) QKV GEMM -> split fp16, head-major, q pre-scaled
    gemm_mma<1><<<dim3(QKVN / 96, MROWS / 128), 128, GEMM_SMEM>>>(
        ah, al, wath, b_attn, nullptr, QKVN, sh, sl);

    // 2) fp16 tensor-core causal flash attention -> att split (reuses ah/al)
    flash_mma<<<dim3(SEQ / 128, NH, BATCH), 128, FLASH_SMEM>>>(sh, sl, ah, al);

    // 3) projection GEMM -> out fp32
    gemm_mma<0><<<dim3(EMB / 96, MROWS / 128), 128, GEMM_SMEM>>>(
        ah, al, wpth, b_proj, out, EMB, nullptr, nullptr);
}

// round 16
// speedup vs baseline: 2.0006x; 1.4303x over previous
#include <cuda_runtime.h>
#include <cuda_fp16.h>
#include <cstdint>
#include <math.h>

#define EMB   768
#define NH    12
#define HD    64
#define BATCH 8
#define SEQ   1024
#define MROWS (BATCH * SEQ)      // 8192
#define QKVN  (3 * EMB)          // 2304

// 0.125 (1/sqrt(64)) * log2(e): folded into Q so softmax uses ex2
#define QSCALE 0.18033688011112042f

#define TSTRIDE ((size_t)BATCH * NH * SEQ * HD)   // elems per q/k/v tensor

// ---------------------------------------------------------------------------
// Scratch (no allocations allowed) — single fp16 planes
// ---------------------------------------------------------------------------
__device__ __align__(256) __half g_Xh[(size_t)MROWS * EMB];    // x, then att
__device__ __align__(256) __half g_WaTh[(size_t)QKVN * EMB];
__device__ __align__(256) __half g_WpTh[(size_t)EMB * EMB];
__device__ __align__(256) __half g_Sh[3 * TSTRIDE];            // q/k/v head-major

// ---------------------------------------------------------------------------
// PTX helpers (sm_80-class only; toolchain targets plain sm_103)
// ---------------------------------------------------------------------------
__device__ __forceinline__ uint32_t smem_u32(const void* p) {
    uint32_t a;
    asm("{ .reg .u64 t; cvta.to.shared.u64 t, %1; cvt.u32.u64 %0, t; }"
        : "=r"(a) : "l"(p));
    return a;
}
__device__ __forceinline__ void cp16(uint32_t dst, const void* src) {
    asm volatile("cp.async.cg.shared.global [%0], [%1], 16;"
                 :: "r"(dst), "l"(src) : "memory");
}
#define CP_COMMIT() asm volatile("cp.async.commit_group;" ::: "memory")
#define CP_WAIT(n)  asm volatile("cp.async.wait_group %0;" :: "n"(n) : "memory")

#define LDSM_X4(r0, r1, r2, r3, addr) \
    asm volatile("ldmatrix.sync.aligned.m8n8.x4.shared.b16 {%0,%1,%2,%3}, [%4];" \
                 : "=r"(r0), "=r"(r1), "=r"(r2), "=r"(r3) : "r"(addr))
#define LDSM_X4T(r0, r1, r2, r3, addr) \
    asm volatile("ldmatrix.sync.aligned.m8n8.x4.trans.shared.b16 {%0,%1,%2,%3}, [%4];" \
                 : "=r"(r0), "=r"(r1), "=r"(r2), "=r"(r3) : "r"(addr))

// fp16 inputs, fp32 accumulate
__device__ __forceinline__ void mma16816(float* d,
                                         uint32_t a0, uint32_t a1, uint32_t a2, uint32_t a3,
                                         uint32_t b0, uint32_t b1) {
    asm volatile("mma.sync.aligned.m16n8k16.row.col.f32.f16.f16.f32 "
                 "{%0,%1,%2,%3}, {%4,%5,%6,%7}, {%8,%9}, {%0,%1,%2,%3};"
                 : "+f"(d[0]), "+f"(d[1]), "+f"(d[2]), "+f"(d[3])
                 : "r"(a0), "r"(a1), "r"(a2), "r"(a3), "r"(b0), "r"(b1));
}

__device__ __forceinline__ float ex2f(float x) {
    float y;
    asm("ex2.approx.ftz.f32 %0, %1;" : "=f"(y) : "f"(x));
    return y;
}

// pack two fp32 -> f16x2 (low = p0)
__device__ __forceinline__ uint32_t pack_f16x2(float p0, float p1) {
    uint32_t h;
    asm("cvt.rn.f16x2.f32 %0, %1, %2;" : "=r"(h) : "f"(p1), "f"(p0));
    return h;
}

// ---------------------------------------------------------------------------
// Prologue kernels
// ---------------------------------------------------------------------------
__global__ __launch_bounds__(256) void cvt_half(const float* __restrict__ src,
                                                __half* __restrict__ dst, int n)
{
    int i = blockIdx.x * blockDim.x + threadIdx.x;
    if (i < n) dst[i] = __float2half_rn(src[i]);
}

// Transpose: W [K,N] fp32 -> Th [N,K] fp16
__global__ __launch_bounds__(256) void transpose_hi(
    const float* __restrict__ W, __half* __restrict__ Th, int K, int N)
{
    __shared__ float t[32][33];
    int k0 = blockIdx.y * 32, n0 = blockIdx.x * 32;
#pragma unroll
    for (int r = 0; r < 32; r += 8) {
        int k = k0 + threadIdx.y + r;
        int n = n0 + threadIdx.x;
        t[threadIdx.y + r][threadIdx.x] = W[(size_t)k * N + n];
    }
    __syncthreads();
#pragma unroll
    for (int r = 0; r < 32; r += 8) {
        int n = n0 + threadIdx.y + r;
        int k = k0 + threadIdx.x;
        Th[(size_t)n * K + k] = __float2half_rn(t[threadIdx.x][threadIdx.y + r]);
    }
}

// ---------------------------------------------------------------------------
// Single-pass fp16 mma.sync GEMM: C = A @ B^T (+bias), fp32 accum.
// CTA tile 128x192, 128 threads, 4 warps (2M x 2N), warp tile 64x96.
// Stage: Ah 16K + Bh 24K = 40 KB; 2 stages = 80 KB -> 2 CTAs/SM.
// MODE 0: fp32 out + bias.  MODE 1: qkv epilogue (fp16 + head-major scatter).
// ---------------------------------------------------------------------------
#define AH_OFF      0
#define BH_OFF      16384
#define STAGE_BYTES 40960
#define GEMM_SMEM   (2 * STAGE_BYTES + 256)
#define NCHUNK      12

template <int MODE>
__global__ __launch_bounds__(128, 2) void gemm_mma(
    const __half* __restrict__ Ah, const __half* __restrict__ Bh,
    const float* __restrict__ bias, float* __restrict__ C, int N,
    __half* __restrict__ outh)
{
    extern __shared__ char sm_raw[];
    const uint32_t base = (smem_u32(sm_raw) + 127) & ~127u;

    const int tid  = threadIdx.x;
    const int lane = tid & 31;
    const int w    = tid >> 5;
    const int wm   = w & 1;               // 64-row slice
    const int wn   = w >> 1;              // 96-col slice
    const int bn   = blockIdx.x;
    const int bm   = blockIdx.y;

    const __half* Abh = Ah + (size_t)bm * 128 * EMB;
    const __half* Bbh = Bh + (size_t)bn * 192 * EMB;

    float acc[4][12][4];
#pragma unroll
    for (int mt = 0; mt < 4; mt++)
#pragma unroll
        for (int nt = 0; nt < 12; nt++)
#pragma unroll
            for (int e = 0; e < 4; e++) acc[mt][nt][e] = 0.0f;

    auto prefetch = [&](int c) {
        const uint32_t stg = base + (uint32_t)(c & 1) * STAGE_BYTES;
        const int koff = c * 64;
        // A tile: 128 rows x 8 segs = 1024 units / 128 thr = 8
#pragma unroll
        for (int j = 0; j < 8; j++) {
            int idx = tid + 128 * j;
            int row = idx >> 3;
            int s   = idx & 7;
            uint32_t off = (uint32_t)(row * 128 + ((s ^ (row & 7)) << 4));
            cp16(stg + AH_OFF + off, Abh + (size_t)row * EMB + koff + s * 8);
        }
        // B tile: 192 rows x 8 segs = 1536 units / 128 thr = 12
#pragma unroll
        for (int j = 0; j < 12; j++) {
            int idx = tid + 128 * j;
            int row = idx >> 3;
            int s   = idx & 7;
            uint32_t off = (uint32_t)(row * 128 + ((s ^ (row & 7)) << 4));
            cp16(stg + BH_OFF + off, Bbh + (size_t)row * EMB + koff + s * 8);
        }
    };

    prefetch(0);
    CP_COMMIT();

    const int qm = lane >> 3;
    const int r8 = lane & 7;

    for (int c = 0; c < NCHUNK; c++) {
        const uint32_t stg = base + (uint32_t)(c & 1) * STAGE_BYTES;

        if (c + 1 < NCHUNK) {
            prefetch(c + 1);
            CP_COMMIT();
            CP_WAIT(1);
        } else {
            CP_WAIT(0);
        }
        __syncthreads();

#pragma unroll
        for (int u = 0; u < 2; u++) {
            uint32_t ah[4][2][4];
#pragma unroll
            for (int mt = 0; mt < 4; mt++)
#pragma unroll
                for (int ks = 0; ks < 2; ks++) {
                    int arow = wm * 64 + mt * 16 + (qm & 1) * 8 + r8;
                    int aseg = (2 * u + ks) * 2 + (qm >> 1);
                    uint32_t sw = arow * 128 + ((aseg ^ (arow & 7)) << 4);
                    LDSM_X4(ah[mt][ks][0], ah[mt][ks][1], ah[mt][ks][2], ah[mt][ks][3],
                            stg + AH_OFF + sw);
                }
#pragma unroll
            for (int nt = 0; nt < 12; nt++) {
                int brow = wn * 96 + nt * 8 + r8;
                int bseg = u * 4 + qm;
                uint32_t t0, t1, t2, t3;
                LDSM_X4(t0, t1, t2, t3,
                        stg + BH_OFF + brow * 128 + ((bseg ^ (brow & 7)) << 4));
#pragma unroll
                for (int mt = 0; mt < 4; mt++) {
                    mma16816(acc[mt][nt], ah[mt][0][0], ah[mt][0][1],
                             ah[mt][0][2], ah[mt][0][3], t0, t1);
                    mma16816(acc[mt][nt], ah[mt][1][0], ah[mt][1][1],
                             ah[mt][1][2], ah[mt][1][3], t2, t3);
                }
            }
        }
        __syncthreads();
    }

    // ---- epilogue ----
    const int row0 = bm * 128 + wm * 64 + (lane >> 2);
    const int col0 = bn * 192 + wn * 96 + 2 * (lane & 3);
#pragma unroll
    for (int mt = 0; mt < 4; mt++)
#pragma unroll
        for (int nt = 0; nt < 12; nt++) {
            int rr = row0 + mt * 16;
            int cc = col0 + nt * 8;
            float b0 = bias[cc], b1 = bias[cc + 1];
            float v0 = acc[mt][nt][0] + b0, v1 = acc[mt][nt][1] + b1;
            float v2 = acc[mt][nt][2] + b0, v3 = acc[mt][nt][3] + b1;
            if (MODE == 0) {
                *(float2*)&C[(size_t)rr * N + cc]       = make_float2(v0, v1);
                *(float2*)&C[(size_t)(rr + 8) * N + cc] = make_float2(v2, v3);
            } else {
                int tensor = cc / 768;
                int within = cc % 768;
                int hh = within >> 6, dd = within & 63;
                if (tensor == 0) { v0 *= QSCALE; v1 *= QSCALE; v2 *= QSCALE; v3 *= QSCALE; }
                {
                    int bb = rr >> 10, t = rr & 1023;
                    size_t di = (size_t)tensor * TSTRIDE +
                                (size_t)(bb * NH + hh) * (SEQ * HD) + (size_t)t * HD + dd;
                    *(uint32_t*)&outh[di] = pack_f16x2(v0, v1);
                }
                {
                    int rr2 = rr + 8;
                    int bb = rr2 >> 10, t = rr2 & 1023;
                    size_t di = (size_t)tensor * TSTRIDE +
                                (size_t)(bb * NH + hh) * (SEQ * HD) + (size_t)t * HD + dd;
                    *(uint32_t*)&outh[di] = pack_f16x2(v2, v3);
                }
            }
        }
}

// ---------------------------------------------------------------------------
// Single-pass fp16 causal flash attention — 3-stage KV ring (Kh+Vh, 16 KB/slot)
// + Q (16 KB). S = Qh·Kh^T; O += Ph·Vh. fp32 accum + online softmax.
// ---------------------------------------------------------------------------
#define FT_BYTES   8192
#define FSTAGE_F   (2 * FT_BYTES)             // Kh, Vh
#define FQ_OFF     (3 * FSTAGE_F)             // 49152
#define FLASH_SMEM (FQ_OFF + 16384 + 1024)

__device__ __forceinline__ void prefetch_kv(uint32_t dst,
    const __half* __restrict__ Kh, const __half* __restrict__ Vh,
    int kt, int tid)
{
    const __half* srcs[2] = {Kh, Vh};
#pragma unroll
    for (int t2 = 0; t2 < 2; t2++) {
        const __half* src = srcs[t2] + (size_t)(kt * 64) * HD;
#pragma unroll
        for (int jj = 0; jj < 4; jj++) {
            int idx = tid + 128 * jj;
            int row = idx >> 3;
            int s   = idx & 7;
            cp16(dst + t2 * FT_BYTES + row * 128 + ((s ^ (row & 7)) << 4),
                 src + (size_t)row * HD + s * 8);
        }
    }
}

__global__ __launch_bounds__(128, 2) void flash_mma(
    const __half* __restrict__ Sh, __half* __restrict__ ath)
{
    extern __shared__ char sm_raw[];
    const uint32_t base = (smem_u32(sm_raw) + 1023) & ~1023u;

    const int tid  = threadIdx.x;
    const int lane = tid & 31;
    const int w    = tid >> 5;
    const int qm   = lane >> 3;
    const int r8   = lane & 7;
    const int tig  = lane & 3;
    const int gid  = lane >> 2;

    const int qt = (SEQ / 128 - 1) - blockIdx.x;   // heavy tiles first
    const int h  = blockIdx.y;
    const int b  = blockIdx.z;
    const int bh = b * NH + h;
    const int qbase = qt * 128;

    const size_t hb = (size_t)bh * (SEQ * HD);
    const __half* Qhp = Sh + hb;
    const __half* Khp = Sh + TSTRIDE + hb;
    const __half* Vhp = Sh + 2 * TSTRIDE + hb;

    const int lastkt = 2 * qt + 1;

    const uint32_t QH_S = base + FQ_OFF;

    // --- prologue groups: G_Q, G_0, G_1 ---
    {
#pragma unroll
        for (int jj = 0; jj < 8; jj++) {
            int idx = tid + 128 * jj;
            int row = idx >> 3;
            int s   = idx & 7;
            cp16(QH_S + row * 128 + ((s ^ (row & 7)) << 4),
                 Qhp + (size_t)(qbase + row) * HD + s * 8);
        }
        CP_COMMIT();                                   // G_Q
        prefetch_kv(base, Khp, Vhp, 0, tid);
        CP_COMMIT();                                   // G_0
        prefetch_kv(base + FSTAGE_F, Khp, Vhp, 1, tid);
        CP_COMMIT();                                   // G_1
    }

    uint32_t qfh[2][4][4];
    CP_WAIT(2);
    __syncthreads();
#pragma unroll
    for (int mt = 0; mt < 2; mt++)
#pragma unroll
        for (int kk = 0; kk < 4; kk++) {
            int arow = w * 32 + mt * 16 + (qm & 1) * 8 + r8;
            int aseg = kk * 2 + (qm >> 1);
            uint32_t sw = ((aseg ^ (arow & 7)) << 4);
            LDSM_X4(qfh[mt][kk][0], qfh[mt][kk][1], qfh[mt][kk][2], qfh[mt][kk][3],
                    QH_S + arow * 128 + sw);
        }

    float oacc[2][8][4];
#pragma unroll
    for (int mt = 0; mt < 2; mt++)
#pragma unroll
        for (int nt = 0; nt < 8; nt++)
#pragma unroll
            for (int e = 0; e < 4; e++) oacc[mt][nt][e] = 0.0f;
    float mrow[2][2], lrow[2][2];
#pragma unroll
    for (int mt = 0; mt < 2; mt++)
#pragma unroll
        for (int hf = 0; hf < 2; hf++) { mrow[mt][hf] = -1e30f; lrow[mt][hf] = 0.0f; }

    const int wrowmax = qbase + w * 32 + 31;

    for (int kt = 0; kt <= lastkt; kt++) {
        CP_WAIT(1);
        __syncthreads();
        if (kt + 2 <= lastkt)
            prefetch_kv(base + (uint32_t)((kt + 2) % 3) * FSTAGE_F,
                        Khp, Vhp, kt + 2, tid);
        CP_COMMIT();

        const uint32_t SB = base + (uint32_t)(kt % 3) * FSTAGE_F;

        if (kt * 64 <= wrowmax) {
            const uint32_t sKh = SB;
            const uint32_t sVh = SB + FT_BYTES;

            float sacc[2][8][4];
#pragma unroll
            for (int mt = 0; mt < 2; mt++)
#pragma unroll
                for (int nt = 0; nt < 8; nt++)
#pragma unroll
                    for (int e = 0; e < 4; e++) sacc[mt][nt][e] = 0.0f;

#pragma unroll
            for (int u = 0; u < 2; u++)
#pragma unroll
                for (int nt = 0; nt < 8; nt++) {
                    int brow = nt * 8 + r8;
                    int bseg = u * 4 + qm;
                    uint32_t sw = ((bseg ^ (brow & 7)) << 4);
                    uint32_t t0, t1, t2, t3;
                    LDSM_X4(t0, t1, t2, t3, sKh + brow * 128 + sw);
#pragma unroll
                    for (int mt = 0; mt < 2; mt++) {
                        mma16816(sacc[mt][nt], qfh[mt][2 * u][0], qfh[mt][2 * u][1],
                                 qfh[mt][2 * u][2], qfh[mt][2 * u][3], t0, t1);
                        mma16816(sacc[mt][nt], qfh[mt][2 * u + 1][0], qfh[mt][2 * u + 1][1],
                                 qfh[mt][2 * u + 1][2], qfh[mt][2 * u + 1][3], t2, t3);
                    }
                }

            if (kt >= 2 * qt) {
                int qr0 = qbase + w * 32 + gid;
                int kc0 = kt * 64 + 2 * tig;
#pragma unroll
                for (int mt = 0; mt < 2; mt++)
#pragma unroll
                    for (int nt = 0; nt < 8; nt++)
#pragma unroll
                        for (int e = 0; e < 4; e++) {
                            int qr = qr0 + mt * 16 + (e >> 1) * 8;
                            int kc = kc0 + nt * 8 + (e & 1);
                            if (kc > qr) sacc[mt][nt][e] = -1e30f;
                        }
            }

            float corr[2][2], nm[2][2];
#pragma unroll
            for (int mt = 0; mt < 2; mt++)
#pragma unroll
                for (int hf = 0; hf < 2; hf++) {
                    float tm = -1e30f;
#pragma unroll
                    for (int nt = 0; nt < 8; nt++) {
                        tm = fmaxf(tm, sacc[mt][nt][2 * hf]);
                        tm = fmaxf(tm, sacc[mt][nt][2 * hf + 1]);
                    }
                    tm = fmaxf(tm, __shfl_xor_sync(0xffffffffu, tm, 1));
                    tm = fmaxf(tm, __shfl_xor_sync(0xffffffffu, tm, 2));
                    float n = fmaxf(mrow[mt][hf], tm);
                    corr[mt][hf] = ex2f(mrow[mt][hf] - n);
                    nm[mt][hf] = n;
                    mrow[mt][hf] = n;
                }

#pragma unroll
            for (int mt = 0; mt < 2; mt++)
#pragma unroll
                for (int hf = 0; hf < 2; hf++) {
                    float ps = 0.0f;
#pragma unroll
                    for (int nt = 0; nt < 8; nt++) {
                        float p0 = ex2f(sacc[mt][nt][2 * hf]     - nm[mt][hf]);
                        float p1 = ex2f(sacc[mt][nt][2 * hf + 1] - nm[mt][hf]);
                        sacc[mt][nt][2 * hf]     = p0;
                        sacc[mt][nt][2 * hf + 1] = p1;
                        ps += p0 + p1;
                    }
                    lrow[mt][hf] = lrow[mt][hf] * corr[mt][hf] + ps;
                }

#pragma unroll
            for (int mt = 0; mt < 2; mt++)
#pragma unroll
                for (int nt = 0; nt < 8; nt++) {
                    oacc[mt][nt][0] *= corr[mt][0];
                    oacc[mt][nt][1] *= corr[mt][0];
                    oacc[mt][nt][2] *= corr[mt][1];
                    oacc[mt][nt][3] *= corr[mt][1];
                }

            // P -> fp16 A-fragments (hi only)
            uint32_t pah[2][4][4];
#pragma unroll
            for (int mt = 0; mt < 2; mt++)
#pragma unroll
                for (int j = 0; j < 4; j++) {
                    pah[mt][j][0] = pack_f16x2(sacc[mt][2 * j][0],     sacc[mt][2 * j][1]);
                    pah[mt][j][1] = pack_f16x2(sacc[mt][2 * j][2],     sacc[mt][2 * j][3]);
                    pah[mt][j][2] = pack_f16x2(sacc[mt][2 * j + 1][0], sacc[mt][2 * j + 1][1]);
                    pah[mt][j][3] = pack_f16x2(sacc[mt][2 * j + 1][2], sacc[mt][2 * j + 1][3]);
                }

#pragma unroll
            for (int j = 0; j < 4; j++)
#pragma unroll
                for (int dp = 0; dp < 4; dp++) {
                    int rowv = j * 16 + (lane & 15);
                    int segv = dp * 2 + (lane >> 4);
                    uint32_t sw = ((segv ^ (rowv & 7)) << 4);
                    uint32_t t0, t1, t2, t3;
                    LDSM_X4T(t0, t1, t2, t3, sVh + rowv * 128 + sw);
#pragma unroll
                    for (int mt = 0; mt < 2; mt++) {
                        mma16816(oacc[mt][2 * dp], pah[mt][j][0], pah[mt][j][1],
                                 pah[mt][j][2], pah[mt][j][3], t0, t1);
                        mma16816(oacc[mt][2 * dp + 1], pah[mt][j][0], pah[mt][j][1],
                                 pah[mt][j][2], pah[mt][j][3], t2, t3);
                    }
                }
        }
    }

    float inv[2][2];
#pragma unroll
    for (int mt = 0; mt < 2; mt++)
#pragma unroll
        for (int hf = 0; hf < 2; hf++) {
            float lv = lrow[mt][hf];
            lv += __shfl_xor_sync(0xffffffffu, lv, 1);
            lv += __shfl_xor_sync(0xffffffffu, lv, 2);
            inv[mt][hf] = 1.0f / lv;
        }

#pragma unroll
    for (int mt = 0; mt < 2; mt++)
#pragma unroll
        for (int nt = 0; nt < 8; nt++) {
            int t0r = qbase + w * 32 + mt * 16 + gid;
            int col = h * HD + nt * 8 + 2 * tig;
            {
                float v0 = oacc[mt][nt][0] * inv[mt][0];
                float v1 = oacc[mt][nt][1] * inv[mt][0];
                size_t di = (size_t)(b * SEQ + t0r) * EMB + col;
                *(uint32_t*)&ath[di] = pack_f16x2(v0, v1);
            }
            {
                float v2 = oacc[mt][nt][2] * inv[mt][1];
                float v3 = oacc[mt][nt][3] * inv[mt][1];
                size_t di = (size_t)(b * SEQ + t0r + 8) * EMB + col;
                *(uint32_t*)&ath[di] = pack_f16x2(v2, v3);
            }
        }
}

// ---------------------------------------------------------------------------
extern "C" void kernel_launch(void* const* d_in, const int* in_sizes, int n_in,
                              void* d_out, int out_size)
{
    (void)in_sizes; (void)n_in; (void)out_size;
    const float* x      = (const float*)d_in[0];
    const float* W_attn = (const float*)d_in[1];
    const float* b_attn = (const float*)d_in[2];
    const float* W_proj = (const float*)d_in[3];
    const float* b_proj = (const float*)d_in[4];
    float* out = (float*)d_out;

    __half *xh, *wath, *wpth, *sh;
    cudaGetSymbolAddress((void**)&xh, g_Xh);
    cudaGetSymbolAddress((void**)&wath, g_WaTh);
    cudaGetSymbolAddress((void**)&wpth, g_WpTh);
    cudaGetSymbolAddress((void**)&sh, g_Sh);

    cudaFuncSetAttribute(gemm_mma<0>, cudaFuncAttributeMaxDynamicSharedMemorySize, GEMM_SMEM);
    cudaFuncSetAttribute(gemm_mma<1>, cudaFuncAttributeMaxDynamicSharedMemorySize, GEMM_SMEM);
    cudaFuncSetAttribute(flash_mma,  cudaFuncAttributeMaxDynamicSharedMemorySize, FLASH_SMEM);

    // Prologue: convert x; transpose weights (all fp16 single plane)
    {
        int n = MROWS * EMB;
        cvt_half<<<(n + 255) / 256, 256>>>(x, xh, n);
    }
    transpose_hi<<<dim3(QKVN / 32, EMB / 32), dim3(32, 8)>>>(W_attn, wath, EMB, QKVN);
    transpose_hi<<<dim3(EMB / 32, EMB / 32), dim3(32, 8)>>>(W_proj, wpth, EMB, EMB);

    // 1) QKV GEMM -> fp16 head-major, q pre-scaled
    gemm_mma<1><<<dim3(QKVN / 192, MROWS / 128), 128, GEMM_SMEM>>>(
        xh, wath, b_attn, nullptr, QKVN, sh);

    // 2) fp16 tensor-core causal flash attention -> att fp16 (reuses g_Xh)
    flash_mma<<<dim3(SEQ / 128, NH, BATCH), 128, FLASH_SMEM>>>(sh, xh);

    // 3) projection GEMM -> out fp32
    gemm_mma<0><<<dim3(EMB / 192, MROWS / 128), 128, GEMM_SMEM>>>(
        xh, wpth, b_proj, out, EMB, nullptr);
}